// round 1
// baseline (speedup 1.0000x reference)
#include <cuda_runtime.h>
#include <math.h>

#define V_   100000
#define D_   128
#define B_   4096
#define NEG_ 5
#define DI_  170     // int(128*2*2/3)
#define BT_  16      // batch rows per block
#define NBLK (B_ / BT_)   // 256

// ---- device scratch (no allocations allowed) ----
__device__ __align__(16) float g_Wh[DI_ * D_];    // row-normalized W_hidden * hidden_scale
__device__ __align__(16) float g_Wg[DI_ * D_];    // row-normalized W_gate * gate_scale * sqrt(D)
__device__ __align__(16) float g_WffT[DI_ * D_];  // W_ff_out col-normalized, transposed to [DI][D]
__device__ float g_partial[NBLK];

// ------------------------------------------------------------------
// Prep: fold all static normalizations/scales into scratch weights.
// 510 warp-tasks: 170 Wh rows, 170 Wg rows, 170 Wff columns.
// ------------------------------------------------------------------
__global__ __launch_bounds__(256) void prep_kernel(
    const float* __restrict__ Wh, const float* __restrict__ Wg,
    const float* __restrict__ Wff,
    const float* __restrict__ hs, const float* __restrict__ gs)
{
    int warp = (blockIdx.x * blockDim.x + threadIdx.x) >> 5;
    int lane = threadIdx.x & 31;
    if (warp >= 3 * DI_) return;
    int mat = warp / DI_;
    int r   = warp - mat * DI_;

    if (mat < 2) {
        const float* W = (mat == 0) ? Wh : Wg;
        float v[4]; float ss = 0.f;
        #pragma unroll
        for (int k = 0; k < 4; k++) {
            v[k] = W[r * D_ + lane + 32 * k];
            ss += v[k] * v[k];
        }
        #pragma unroll
        for (int o = 16; o; o >>= 1) ss += __shfl_xor_sync(0xffffffffu, ss, o);
        float scale = rsqrtf(ss) * ((mat == 0) ? hs[r] : gs[r] * 11.3137084989847604f /*sqrt(128)*/);
        float* dst = (mat == 0) ? g_Wh : g_Wg;
        #pragma unroll
        for (int k = 0; k < 4; k++) dst[r * D_ + lane + 32 * k] = v[k] * scale;
    } else {
        // column r of W_ff_out [D_ x DI_], normalize over D, store transposed
        float v[4]; float ss = 0.f;
        #pragma unroll
        for (int k = 0; k < 4; k++) {
            int d = lane + 32 * k;
            v[k] = Wff[d * DI_ + r];
            ss += v[k] * v[k];
        }
        #pragma unroll
        for (int o = 16; o; o >>= 1) ss += __shfl_xor_sync(0xffffffffu, ss, o);
        float inv = rsqrtf(ss);
        #pragma unroll
        for (int k = 0; k < 4; k++) {
            int d = lane + 32 * k;
            g_WffT[r * D_ + d] = v[k] * inv;
        }
    }
}

// ------------------------------------------------------------------
// Main: one block = 16 batch rows, 256 threads.
// ------------------------------------------------------------------
__global__ __launch_bounds__(256) void main_kernel(
    const int*   __restrict__ input_ids,
    const int*   __restrict__ target_ids,
    const int*   __restrict__ neg_ids,
    const float* __restrict__ W_in,
    const float* __restrict__ W_out,
    const float* __restrict__ logit_scale)
{
    __shared__ __align__(16) float emb[BT_][132];   // 132*4 = 528B row stride (16B aligned)
    __shared__ __align__(16) float a_sh[BT_][172];
    __shared__ __align__(16) float x_sh[BT_][132];
    __shared__ float warpacc[8];

    const int tid  = threadIdx.x;
    const int lane = tid & 31;
    const int warp = tid >> 5;
    const int b0   = blockIdx.x * BT_;

    // ---- Phase 1: gather + l2-normalize input embeddings (warp per row) ----
    for (int bb = warp; bb < BT_; bb += 8) {
        int row = input_ids[b0 + bb];
        const float* w = W_in + (size_t)row * D_;
        float v[4]; float ss = 0.f;
        #pragma unroll
        for (int k = 0; k < 4; k++) {
            v[k] = w[lane + 32 * k];
            ss += v[k] * v[k];
        }
        #pragma unroll
        for (int o = 16; o; o >>= 1) ss += __shfl_xor_sync(0xffffffffu, ss, o);
        float inv = rsqrtf(ss);
        #pragma unroll
        for (int k = 0; k < 4; k++) emb[bb][lane + 32 * k] = v[k] * inv;
    }
    __syncthreads();

    // ---- Phase 2: a[b][i] = silu(g)*h ; each thread keeps fixed b, strides i ----
    for (int idx = tid; idx < BT_ * DI_; idx += 256) {
        int b = idx & (BT_ - 1);
        int i = idx >> 4;
        const float4* e4  = (const float4*)emb[b];
        const float4* wh4 = (const float4*)&g_Wh[i * D_];
        const float4* wg4 = (const float4*)&g_Wg[i * D_];
        float h = 0.f, g = 0.f;
        #pragma unroll 8
        for (int d4 = 0; d4 < D_ / 4; d4++) {
            float4 ev = e4[d4];
            float4 wh = wh4[d4];
            float4 wg = wg4[d4];
            h += ev.x * wh.x + ev.y * wh.y + ev.z * wh.z + ev.w * wh.w;
            g += ev.x * wg.x + ev.y * wg.y + ev.z * wg.z + ev.w * wg.w;
        }
        float sg = g / (1.f + __expf(-g));   // silu(g)
        a_sh[b][i] = sg * h;
    }
    __syncthreads();

    // ---- Phase 3: x[b][d] = sum_i a[b][i] * WffT[i][d] ----
    {
        int d      = tid & (D_ - 1);
        int bstart = tid >> 7;               // 0 or 1
        float acc[8];
        #pragma unroll
        for (int k = 0; k < 8; k++) acc[k] = 0.f;
        #pragma unroll 2
        for (int i = 0; i < DI_; i++) {
            float w = g_WffT[i * D_ + d];    // coalesced across warp
            #pragma unroll
            for (int k = 0; k < 8; k++)
                acc[k] += a_sh[bstart + 2 * k][i] * w;   // smem broadcast
        }
        #pragma unroll
        for (int k = 0; k < 8; k++) x_sh[bstart + 2 * k][d] = acc[k];
    }
    __syncthreads();

    // ---- Phase 4: 6 gathered logits per row, log-sigmoid, reduce ----
    float local = 0.f;
    for (int t = warp; t < BT_ * 6; t += 8) {
        int b = t / 6, j = t - 6 * b;
        int gb = b0 + b;
        int row = (j == 0) ? target_ids[gb] : neg_ids[gb * NEG_ + (j - 1)];
        const float* w = W_out + (size_t)row * D_;
        const float* x = x_sh[b];
        float dot = 0.f, ss = 0.f;
        #pragma unroll
        for (int k = 0; k < 4; k++) {
            float wv = w[lane + 32 * k];
            dot += wv * x[lane + 32 * k];
            ss  += wv * wv;
        }
        #pragma unroll
        for (int o = 16; o; o >>= 1) {
            dot += __shfl_xor_sync(0xffffffffu, dot, o);
            ss  += __shfl_xor_sync(0xffffffffu, ss, o);
        }
        if (lane == 0) {
            float logit = dot * rsqrtf(ss) * logit_scale[row] * 11.3137084989847604f;
            float z = (j == 0) ? logit : -logit;
            float ls = fminf(z, 0.f) - log1pf(__expf(-fabsf(z)));
            local += ls * ((j == 0) ? (1.f / B_) : (1.f / (B_ * NEG_)));
        }
    }
    if (lane == 0) warpacc[warp] = local;
    __syncthreads();
    if (tid == 0) {
        float s = 0.f;
        #pragma unroll
        for (int w = 0; w < 8; w++) s += warpacc[w];
        g_partial[blockIdx.x] = s;   // deterministic: one slot per block
    }
}

// ------------------------------------------------------------------
// Finalize: deterministic tree reduction of 256 block partials.
// ------------------------------------------------------------------
__global__ void finalize_kernel(float* __restrict__ out)
{
    __shared__ float s[NBLK];
    s[threadIdx.x] = g_partial[threadIdx.x];
    __syncthreads();
    #pragma unroll
    for (int o = NBLK / 2; o; o >>= 1) {
        if (threadIdx.x < o) s[threadIdx.x] += s[threadIdx.x + o];
        __syncthreads();
    }
    if (threadIdx.x == 0) out[0] = -s[0];
}

extern "C" void kernel_launch(void* const* d_in, const int* in_sizes, int n_in,
                              void* d_out, int out_size)
{
    const int*   input_ids   = (const int*)  d_in[0];
    const int*   target_ids  = (const int*)  d_in[1];
    const int*   neg_ids     = (const int*)  d_in[2];
    const float* W_in        = (const float*)d_in[3];
    const float* W_out       = (const float*)d_in[4];
    const float* W_hidden    = (const float*)d_in[5];
    const float* W_gate      = (const float*)d_in[6];
    const float* W_ff_out    = (const float*)d_in[7];
    const float* hidden_sc   = (const float*)d_in[8];
    const float* gate_sc     = (const float*)d_in[9];
    const float* logit_scale = (const float*)d_in[10];
    float* out = (float*)d_out;

    prep_kernel<<<64, 256>>>(W_hidden, W_gate, W_ff_out, hidden_sc, gate_sc);
    main_kernel<<<NBLK, 256>>>(input_ids, target_ids, neg_ids, W_in, W_out, logit_scale);
    finalize_kernel<<<1, NBLK>>>(out);
}

// round 2
// speedup vs baseline: 1.4920x; 1.4920x over previous
#include <cuda_runtime.h>
#include <math.h>

#define V_   100000
#define D_   128
#define B_   4096
#define NEG_ 5
#define DI_  170
#define BT_  32
#define NBLK (B_ / BT_)      // 128
#define TI_  85              // i-tile (2 passes)

typedef unsigned long long u64;

// packed f32x2 helpers
__device__ __forceinline__ u64 fma2(u64 a, u64 b, u64 c) {
    u64 d;
    asm("fma.rn.f32x2 %0, %1, %2, %3;" : "=l"(d) : "l"(a), "l"(b), "l"(c));
    return d;
}
__device__ __forceinline__ u64 pk2(float lo, float hi) {
    u64 r;
    asm("mov.b64 %0, {%1, %2};" : "=l"(r) : "f"(lo), "f"(hi));
    return r;
}
__device__ __forceinline__ float2 unpk(u64 v) {
    float2 r;
    asm("mov.b64 {%0, %1}, %2;" : "=f"(r.x), "=f"(r.y) : "l"(v));
    return r;
}

// ---- device scratch ----
__device__ __align__(16) float4 g_Whg[DI_ * 64];   // [i][d4][{wh4,wg4}] interleaved
__device__ __align__(16) float  g_WffT[DI_ * D_];  // col-normalized, transposed [DI][D]
__device__ float g_partial[NBLK];

// ------------------------------------------------------------------
// Prep: fold normalizations/scales, write interleaved Whg + WffT.
// ------------------------------------------------------------------
__global__ __launch_bounds__(256) void prep_kernel(
    const float* __restrict__ Wh, const float* __restrict__ Wg,
    const float* __restrict__ Wff,
    const float* __restrict__ hs, const float* __restrict__ gs)
{
    int warp = (blockIdx.x * blockDim.x + threadIdx.x) >> 5;
    int lane = threadIdx.x & 31;
    if (warp >= 3 * DI_) return;
    int mat = warp / DI_;
    int r   = warp - mat * DI_;

    if (mat < 2) {
        const float4* W = (const float4*)((mat == 0) ? Wh : Wg);
        float4 v = W[r * 32 + lane];
        float ss = v.x * v.x + v.y * v.y + v.z * v.z + v.w * v.w;
        #pragma unroll
        for (int o = 16; o; o >>= 1) ss += __shfl_xor_sync(0xffffffffu, ss, o);
        float sc = rsqrtf(ss) * ((mat == 0) ? hs[r] : gs[r] * 11.3137084989847604f);
        float4 o4 = make_float4(v.x * sc, v.y * sc, v.z * sc, v.w * sc);
        g_Whg[r * 64 + lane * 2 + mat] = o4;
    } else {
        float v[4]; float ss = 0.f;
        #pragma unroll
        for (int k = 0; k < 4; k++) {
            int d = lane + 32 * k;
            v[k] = Wff[d * DI_ + r];
            ss += v[k] * v[k];
        }
        #pragma unroll
        for (int o = 16; o; o >>= 1) ss += __shfl_xor_sync(0xffffffffu, ss, o);
        float inv = rsqrtf(ss);
        #pragma unroll
        for (int k = 0; k < 4; k++) g_WffT[r * D_ + lane + 32 * k] = v[k] * inv;
    }
}

// ------------------------------------------------------------------
// Main: one block = 32 batch rows, 256 threads, ~145KB dynamic smem.
// ------------------------------------------------------------------
// smem layout (bytes):
//   whg_s : float4[TI_*66]        0      .. 89760   (66 f4/row: 64 data + 2 pad)
//   emb_i : float4[1024]          89760  .. 106144  (idx = d4*32 + k*8 + bg)
//   a_t   : float [DI_*32]        106144 .. 127904
//   x_s   : float [32*132]        127904 .. 144800
//   wacc  : float [8]             144800 .. 144832
// wff_s (float[DI_*128] = 87040B) aliases whg_s after phase 2.
#define SMEM_BYTES 144832

__global__ __launch_bounds__(256) void main_kernel(
    const int*   __restrict__ input_ids,
    const int*   __restrict__ target_ids,
    const int*   __restrict__ neg_ids,
    const float* __restrict__ W_in,
    const float* __restrict__ W_out,
    const float* __restrict__ logit_scale)
{
    extern __shared__ __align__(16) char smem[];
    float4* whg_s = (float4*)smem;
    float4* emb_i = (float4*)(smem + 89760);
    float*  a_t   = (float*)(smem + 106144);
    float*  x_s   = (float*)(smem + 127904);
    float*  wacc  = (float*)(smem + 144800);
    float*  wff_s = (float*)smem;  // alias, used after phase 2

    const int tid  = threadIdx.x;
    const int lane = tid & 31;
    const int warp = tid >> 5;
    const int b0   = blockIdx.x * BT_;

    // ---- Phase 1: gather + l2-normalize 32 input embeddings (4 per warp, MLP) ----
    {
        int rows[4]; float4 v[4];
        #pragma unroll
        for (int r = 0; r < 4; r++) rows[r] = input_ids[b0 + warp * 4 + r];
        #pragma unroll
        for (int r = 0; r < 4; r++)
            v[r] = ((const float4*)(W_in + (size_t)rows[r] * D_))[lane];
        #pragma unroll
        for (int r = 0; r < 4; r++) {
            float ss = v[r].x * v[r].x + v[r].y * v[r].y + v[r].z * v[r].z + v[r].w * v[r].w;
            #pragma unroll
            for (int o = 16; o; o >>= 1) ss += __shfl_xor_sync(0xffffffffu, ss, o);
            float inv = rsqrtf(ss);
            int b = warp * 4 + r;
            // emb_i[d4*32 + k*8 + bg] where b = 4*bg + k, d4 = lane
            emb_i[lane * 32 + (b & 3) * 8 + (b >> 2)] =
                make_float4(v[r].x * inv, v[r].y * inv, v[r].z * inv, v[r].w * inv);
        }
    }
    __syncthreads();

    // ---- Phase 2: a[b][i] = silu(g)*h, 2 passes over i-tiles ----
    #pragma unroll 1
    for (int pass = 0; pass < 2; pass++) {
        // stage whg tile (coalesced, pad 2 f4 per i-row for bank spread)
        const float4* src = g_Whg + pass * TI_ * 64;
        for (int f = tid; f < TI_ * 64; f += 256)
            whg_s[(f >> 6) * 66 + (f & 63)] = src[f];
        __syncthreads();

        for (int idx = tid; idx < TI_ * 8; idx += 256) {
            int bg = idx & 7;
            int il = idx >> 3;
            int i  = pass * TI_ + il;
            const ulonglong2* wrow = (const ulonglong2*)&whg_s[il * 66];
            const ulonglong2* eb   = (const ulonglong2*)emb_i;
            u64 hacc[4] = {0, 0, 0, 0};
            u64 gacc[4] = {0, 0, 0, 0};
            #pragma unroll 8
            for (int d4 = 0; d4 < 32; d4++) {
                ulonglong2 wh = wrow[d4 * 2];
                ulonglong2 wg = wrow[d4 * 2 + 1];
                #pragma unroll
                for (int k = 0; k < 4; k++) {
                    ulonglong2 ev = eb[d4 * 32 + k * 8 + bg];
                    hacc[k] = fma2(ev.x, wh.x, hacc[k]);
                    hacc[k] = fma2(ev.y, wh.y, hacc[k]);
                    gacc[k] = fma2(ev.x, wg.x, gacc[k]);
                    gacc[k] = fma2(ev.y, wg.y, gacc[k]);
                }
            }
            #pragma unroll
            for (int k = 0; k < 4; k++) {
                float2 hp = unpk(hacc[k]);
                float2 gp = unpk(gacc[k]);
                float h = hp.x + hp.y;
                float g = gp.x + gp.y;
                float sg = g / (1.f + __expf(-g));
                a_t[i * 32 + 4 * bg + k] = sg * h;
            }
        }
        __syncthreads();
    }

    // ---- stage WffT into reused smem buffer ----
    {
        const float4* src = (const float4*)g_WffT;
        float4* dst = (float4*)wff_s;
        for (int f = tid; f < DI_ * 32; f += 256) dst[f] = src[f];
    }
    __syncthreads();

    // ---- Phase 3: x[b][d] = sum_i a[b][i] * WffT[i][d]; 128 threads, b-pair packed ----
    if (tid < 128) {
        int d = tid;
        u64 acc[16];
        #pragma unroll
        for (int p = 0; p < 16; p++) acc[p] = 0;
        #pragma unroll 2
        for (int i = 0; i < DI_; i++) {
            float w = wff_s[i * D_ + d];
            u64 ww = pk2(w, w);
            const ulonglong2* ar = (const ulonglong2*)&a_t[i * 32];
            #pragma unroll
            for (int q = 0; q < 8; q++) {
                ulonglong2 aa = ar[q];           // pairs (b=4q,4q+1),(4q+2,4q+3)
                acc[2 * q]     = fma2(aa.x, ww, acc[2 * q]);
                acc[2 * q + 1] = fma2(aa.y, ww, acc[2 * q + 1]);
            }
        }
        #pragma unroll
        for (int p = 0; p < 16; p++) {
            float2 xp = unpk(acc[p]);
            x_s[(2 * p) * 132 + d]     = xp.x;
            x_s[(2 * p + 1) * 132 + d] = xp.y;
        }
    }
    __syncthreads();

    // ---- Phase 4: 6 gathered logits per row (chunked preload for MLP) ----
    float local = 0.f;
    #pragma unroll 1
    for (int c = 0; c < 4; c++) {
        int b  = warp * 4 + c;
        int gb = b0 + b;
        int rows[6]; float4 wv[6]; float lsc[6];
        #pragma unroll
        for (int j = 0; j < 6; j++)
            rows[j] = (j == 0) ? target_ids[gb] : neg_ids[gb * NEG_ + (j - 1)];
        #pragma unroll
        for (int j = 0; j < 6; j++)
            wv[j] = ((const float4*)(W_out + (size_t)rows[j] * D_))[lane];
        #pragma unroll
        for (int j = 0; j < 6; j++) lsc[j] = logit_scale[rows[j]];

        float4 x4 = ((const float4*)(x_s + b * 132))[lane];
        #pragma unroll
        for (int j = 0; j < 6; j++) {
            float dot = wv[j].x * x4.x + wv[j].y * x4.y + wv[j].z * x4.z + wv[j].w * x4.w;
            float ss  = wv[j].x * wv[j].x + wv[j].y * wv[j].y + wv[j].z * wv[j].z + wv[j].w * wv[j].w;
            #pragma unroll
            for (int o = 16; o; o >>= 1) {
                dot += __shfl_xor_sync(0xffffffffu, dot, o);
                ss  += __shfl_xor_sync(0xffffffffu, ss, o);
            }
            if (lane == 0) {
                float logit = dot * rsqrtf(ss) * lsc[j] * 11.3137084989847604f;
                float z = (j == 0) ? logit : -logit;
                float ls = fminf(z, 0.f) - log1pf(__expf(-fabsf(z)));
                local += ls * ((j == 0) ? (1.f / B_) : (1.f / (B_ * NEG_)));
            }
        }
    }
    if (lane == 0) wacc[warp] = local;
    __syncthreads();
    if (tid == 0) {
        float s = 0.f;
        #pragma unroll
        for (int w = 0; w < 8; w++) s += wacc[w];
        g_partial[blockIdx.x] = s;
    }
}

// ------------------------------------------------------------------
__global__ void finalize_kernel(float* __restrict__ out)
{
    __shared__ float s[NBLK];
    s[threadIdx.x] = g_partial[threadIdx.x];
    __syncthreads();
    #pragma unroll
    for (int o = NBLK / 2; o; o >>= 1) {
        if (threadIdx.x < o) s[threadIdx.x] += s[threadIdx.x + o];
        __syncthreads();
    }
    if (threadIdx.x == 0) out[0] = -s[0];
}

extern "C" void kernel_launch(void* const* d_in, const int* in_sizes, int n_in,
                              void* d_out, int out_size)
{
    const int*   input_ids   = (const int*)  d_in[0];
    const int*   target_ids  = (const int*)  d_in[1];
    const int*   neg_ids     = (const int*)  d_in[2];
    const float* W_in        = (const float*)d_in[3];
    const float* W_out       = (const float*)d_in[4];
    const float* W_hidden    = (const float*)d_in[5];
    const float* W_gate      = (const float*)d_in[6];
    const float* W_ff_out    = (const float*)d_in[7];
    const float* hidden_sc   = (const float*)d_in[8];
    const float* gate_sc     = (const float*)d_in[9];
    const float* logit_scale = (const float*)d_in[10];
    float* out = (float*)d_out;

    cudaFuncSetAttribute(main_kernel, cudaFuncAttributeMaxDynamicSharedMemorySize, SMEM_BYTES);

    prep_kernel<<<64, 256>>>(W_hidden, W_gate, W_ff_out, hidden_sc, gate_sc);
    main_kernel<<<NBLK, 256, SMEM_BYTES>>>(input_ids, target_ids, neg_ids, W_in, W_out, logit_scale);
    finalize_kernel<<<1, NBLK>>>(out);
}

// round 3
// speedup vs baseline: 1.4987x; 1.0045x over previous
#include <cuda_runtime.h>
#include <math.h>

#define V_   100000
#define D_   128
#define B_   4096
#define NEG_ 5
#define DI_  170
#define BT_  32
#define NBLK (B_ / BT_)      // 128
#define TI_  85              // i-tile (2 passes)
#define THREADS 512

typedef unsigned long long u64;

__device__ __forceinline__ u64 fma2(u64 a, u64 b, u64 c) {
    u64 d;
    asm("fma.rn.f32x2 %0, %1, %2, %3;" : "=l"(d) : "l"(a), "l"(b), "l"(c));
    return d;
}
__device__ __forceinline__ u64 pk2(float lo, float hi) {
    u64 r;
    asm("mov.b64 %0, {%1, %2};" : "=l"(r) : "f"(lo), "f"(hi));
    return r;
}
__device__ __forceinline__ float2 unpk(u64 v) {
    float2 r;
    asm("mov.b64 {%0, %1}, %2;" : "=f"(r.x), "=f"(r.y) : "l"(v));
    return r;
}

// ---- device scratch ----
__device__ __align__(16) float4 g_Whg[DI_ * 64];   // [i][d4][{wh4,wg4}] interleaved
__device__ __align__(16) float  g_WffT[DI_ * D_];  // col-normalized, transposed [DI][D]
__device__ float g_partial[NBLK];
__device__ unsigned int g_ticket;

// ------------------------------------------------------------------
// Prep: one block per i-row (170 blocks x 3 warps), spread across SMs.
// ------------------------------------------------------------------
__global__ __launch_bounds__(96) void prep_kernel(
    const float* __restrict__ Wh, const float* __restrict__ Wg,
    const float* __restrict__ Wff,
    const float* __restrict__ hs, const float* __restrict__ gs)
{
    int r    = blockIdx.x;
    int mat  = threadIdx.x >> 5;
    int lane = threadIdx.x & 31;

    if (mat < 2) {
        const float4* W = (const float4*)((mat == 0) ? Wh : Wg);
        float4 v = W[r * 32 + lane];
        float ss = v.x * v.x + v.y * v.y + v.z * v.z + v.w * v.w;
        #pragma unroll
        for (int o = 16; o; o >>= 1) ss += __shfl_xor_sync(0xffffffffu, ss, o);
        float sc = rsqrtf(ss) * ((mat == 0) ? hs[r] : gs[r] * 11.3137084989847604f);
        g_Whg[r * 64 + lane * 2 + mat] =
            make_float4(v.x * sc, v.y * sc, v.z * sc, v.w * sc);
    } else {
        float v[4]; float ss = 0.f;
        #pragma unroll
        for (int k = 0; k < 4; k++) {
            int d = lane + 32 * k;
            v[k] = Wff[d * DI_ + r];
            ss += v[k] * v[k];
        }
        #pragma unroll
        for (int o = 16; o; o >>= 1) ss += __shfl_xor_sync(0xffffffffu, ss, o);
        float inv = rsqrtf(ss);
        #pragma unroll
        for (int k = 0; k < 4; k++) g_WffT[r * D_ + lane + 32 * k] = v[k] * inv;
    }
}

// ------------------------------------------------------------------
// Main: 128 blocks x 512 threads (16 warps), 32 batch rows per block.
// smem layout (bytes):
//   whg_s : float4[TI_*66]   0      .. 89760
//   emb_i : float4[1024]     89760  .. 106144   (idx = d4*32 + k*8 + bg)
//   a_t   : float [DI_*32]   106144 .. 127904   (a_t[i*32 + b])
//   x_s   : float [32*132]   127904 .. 144800
//   wacc  : float [16]       144800 .. 144864
//   flag  : int              144864 .. 144868
// ------------------------------------------------------------------
#define SMEM_BYTES 144896

__global__ __launch_bounds__(THREADS) void main_kernel(
    const int*   __restrict__ input_ids,
    const int*   __restrict__ target_ids,
    const int*   __restrict__ neg_ids,
    const float* __restrict__ W_in,
    const float* __restrict__ W_out,
    const float* __restrict__ logit_scale,
    float*       __restrict__ out)
{
    extern __shared__ __align__(16) char smem[];
    float4* whg_s = (float4*)smem;
    float4* emb_i = (float4*)(smem + 89760);
    float*  a_t   = (float*)(smem + 106144);
    float*  x_s   = (float*)(smem + 127904);
    float*  wacc  = (float*)(smem + 144800);
    int*    sflag = (int*)(smem + 144864);

    const int tid  = threadIdx.x;
    const int lane = tid & 31;
    const int warp = tid >> 5;
    const int b0   = blockIdx.x * BT_;

    // ---- Phase 1: gather + l2-normalize 32 input embeddings (2 per warp) ----
    {
        #pragma unroll
        for (int r = 0; r < 2; r++) {
            int b   = warp * 2 + r;
            int row = input_ids[b0 + b];
            float4 v = ((const float4*)(W_in + (size_t)row * D_))[lane];
            float ss = v.x * v.x + v.y * v.y + v.z * v.z + v.w * v.w;
            #pragma unroll
            for (int o = 16; o; o >>= 1) ss += __shfl_xor_sync(0xffffffffu, ss, o);
            float inv = rsqrtf(ss);
            emb_i[lane * 32 + (b & 3) * 8 + (b >> 2)] =
                make_float4(v.x * inv, v.y * inv, v.z * inv, v.w * inv);
        }
    }
    __syncthreads();

    // ---- Phase 2: a[b][i] = silu(g)*h, 2 passes over i-tiles ----
    #pragma unroll 1
    for (int pass = 0; pass < 2; pass++) {
        const float4* src = g_Whg + pass * TI_ * 64;
        for (int f = tid; f < TI_ * 64; f += THREADS)
            whg_s[(f >> 6) * 66 + (f & 63)] = src[f];
        __syncthreads();

        for (int idx = tid; idx < TI_ * 8; idx += THREADS) {
            int bg = idx & 7;
            int il = idx >> 3;
            int i  = pass * TI_ + il;
            const ulonglong2* wrow = (const ulonglong2*)&whg_s[il * 66];
            const ulonglong2* eb   = (const ulonglong2*)emb_i;
            u64 hacc[4] = {0, 0, 0, 0};
            u64 gacc[4] = {0, 0, 0, 0};
            #pragma unroll 8
            for (int d4 = 0; d4 < 32; d4++) {
                ulonglong2 wh = wrow[d4 * 2];
                ulonglong2 wg = wrow[d4 * 2 + 1];
                #pragma unroll
                for (int k = 0; k < 4; k++) {
                    ulonglong2 ev = eb[d4 * 32 + k * 8 + bg];
                    hacc[k] = fma2(ev.x, wh.x, hacc[k]);
                    hacc[k] = fma2(ev.y, wh.y, hacc[k]);
                    gacc[k] = fma2(ev.x, wg.x, gacc[k]);
                    gacc[k] = fma2(ev.y, wg.y, gacc[k]);
                }
            }
            #pragma unroll
            for (int k = 0; k < 4; k++) {
                float2 hp = unpk(hacc[k]);
                float2 gp = unpk(gacc[k]);
                float h = hp.x + hp.y;
                float g = gp.x + gp.y;
                float sg = g / (1.f + __expf(-g));
                a_t[i * 32 + 4 * bg + k] = sg * h;
            }
        }
        __syncthreads();
    }

    // ---- Phase 3: x[b][d] = sum_i a[b][i]*WffT[i][d]; 128 d x 4 bq (8 b each) ----
    {
        int d  = tid & 127;
        int bq = tid >> 7;             // 0..3, owns b in [bq*8, bq*8+8)
        u64 acc[4] = {0, 0, 0, 0};
        const float* wcol = g_WffT + d;
        #pragma unroll 2
        for (int i = 0; i < DI_; i++) {
            float w = __ldg(wcol + i * D_);      // coalesced, L1/L2 hot
            u64 ww = pk2(w, w);
            const ulonglong2* ar = (const ulonglong2*)&a_t[i * 32 + bq * 8];
            ulonglong2 a01 = ar[0];
            ulonglong2 a23 = ar[1];
            acc[0] = fma2(a01.x, ww, acc[0]);
            acc[1] = fma2(a01.y, ww, acc[1]);
            acc[2] = fma2(a23.x, ww, acc[2]);
            acc[3] = fma2(a23.y, ww, acc[3]);
        }
        #pragma unroll
        for (int p = 0; p < 4; p++) {
            float2 xp = unpk(acc[p]);
            int b = bq * 8 + 2 * p;
            x_s[b * 132 + d]       = xp.x;
            x_s[(b + 1) * 132 + d] = xp.y;
        }
    }
    __syncthreads();

    // ---- Phase 4: 6 gathered logits per row; warp handles 2 rows ----
    float local = 0.f;
    #pragma unroll
    for (int c = 0; c < 2; c++) {
        int b  = warp * 2 + c;
        int gb = b0 + b;
        int rows[6]; float4 wv[6]; float lsc[6];
        #pragma unroll
        for (int j = 0; j < 6; j++)
            rows[j] = (j == 0) ? target_ids[gb] : neg_ids[gb * NEG_ + (j - 1)];
        #pragma unroll
        for (int j = 0; j < 6; j++)
            wv[j] = ((const float4*)(W_out + (size_t)rows[j] * D_))[lane];
        #pragma unroll
        for (int j = 0; j < 6; j++) lsc[j] = logit_scale[rows[j]];

        float4 x4 = ((const float4*)(x_s + b * 132))[lane];
        #pragma unroll
        for (int j = 0; j < 6; j++) {
            float dot = wv[j].x * x4.x + wv[j].y * x4.y + wv[j].z * x4.z + wv[j].w * x4.w;
            float ss  = wv[j].x * wv[j].x + wv[j].y * wv[j].y + wv[j].z * wv[j].z + wv[j].w * wv[j].w;
            #pragma unroll
            for (int o = 16; o; o >>= 1) {
                dot += __shfl_xor_sync(0xffffffffu, dot, o);
                ss  += __shfl_xor_sync(0xffffffffu, ss, o);
            }
            if (lane == 0) {
                float logit = dot * rsqrtf(ss) * lsc[j] * 11.3137084989847604f;
                float z = (j == 0) ? logit : -logit;
                float ls = fminf(z, 0.f) - log1pf(__expf(-fabsf(z)));
                local += ls * ((j == 0) ? (1.f / B_) : (1.f / (B_ * NEG_)));
            }
        }
    }
    if (lane == 0) wacc[warp] = local;
    __syncthreads();

    // ---- block partial + fused deterministic final reduction ----
    if (tid == 0) {
        float s = 0.f;
        #pragma unroll
        for (int w = 0; w < 16; w++) s += wacc[w];
        g_partial[blockIdx.x] = s;
        __threadfence();
        unsigned int t = atomicAdd(&g_ticket, 1u);
        sflag[0] = (t == NBLK - 1) ? 1 : 0;
    }
    __syncthreads();
    if (sflag[0]) {
        // last block: all partials visible; reduce in fixed order
        __threadfence();
        float* red = x_s;  // reuse smem
        if (tid < NBLK) red[tid] = g_partial[tid];
        __syncthreads();
        #pragma unroll
        for (int o = NBLK / 2; o; o >>= 1) {
            if (tid < o) red[tid] += red[tid + o];
            __syncthreads();
        }
        if (tid == 0) {
            out[0] = -red[0];
            g_ticket = 0;   // reset for next graph replay
        }
    }
}

extern "C" void kernel_launch(void* const* d_in, const int* in_sizes, int n_in,
                              void* d_out, int out_size)
{
    const int*   input_ids   = (const int*)  d_in[0];
    const int*   target_ids  = (const int*)  d_in[1];
    const int*   neg_ids     = (const int*)  d_in[2];
    const float* W_in        = (const float*)d_in[3];
    const float* W_out       = (const float*)d_in[4];
    const float* W_hidden    = (const float*)d_in[5];
    const float* W_gate      = (const float*)d_in[6];
    const float* W_ff_out    = (const float*)d_in[7];
    const float* hidden_sc   = (const float*)d_in[8];
    const float* gate_sc     = (const float*)d_in[9];
    const float* logit_scale = (const float*)d_in[10];
    float* out = (float*)d_out;

    cudaFuncSetAttribute(main_kernel, cudaFuncAttributeMaxDynamicSharedMemorySize, SMEM_BYTES);

    prep_kernel<<<DI_, 96>>>(W_hidden, W_gate, W_ff_out, hidden_sc, gate_sc);
    main_kernel<<<NBLK, THREADS, SMEM_BYTES>>>(input_ids, target_ids, neg_ids,
                                               W_in, W_out, logit_scale, out);
}

// round 4
// speedup vs baseline: 1.5026x; 1.0026x over previous
#include <cuda_runtime.h>
#include <math.h>

#define V_   100000
#define D_   128
#define B_   4096
#define NEG_ 5
#define DI_  170
#define BT_  32
#define NBLK (B_ / BT_)      // 128
#define THREADS 1024

typedef unsigned long long u64;

__device__ __forceinline__ u64 fma2(u64 a, u64 b, u64 c) {
    u64 d;
    asm("fma.rn.f32x2 %0, %1, %2, %3;" : "=l"(d) : "l"(a), "l"(b), "l"(c));
    return d;
}
__device__ __forceinline__ u64 pk2(float lo, float hi) {
    u64 r;
    asm("mov.b64 %0, {%1, %2};" : "=l"(r) : "f"(lo), "f"(hi));
    return r;
}
__device__ __forceinline__ float2 unpk(u64 v) {
    float2 r;
    asm("mov.b64 {%0, %1}, %2;" : "=f"(r.x), "=f"(r.y) : "l"(v));
    return r;
}

// ---- device scratch ----
__device__ __align__(16) float4 g_Whg[DI_ * 64];   // [i][d4][{wh4,wg4}]
__device__ __align__(16) float  g_WffT[DI_ * D_];  // col-normalized, transposed [DI][D]
__device__ float g_partial[NBLK];
__device__ unsigned int g_ticket;

// ------------------------------------------------------------------
// Prep: one block per i-row (170 blocks x 3 warps).
// ------------------------------------------------------------------
__global__ __launch_bounds__(96) void prep_kernel(
    const float* __restrict__ Wh, const float* __restrict__ Wg,
    const float* __restrict__ Wff,
    const float* __restrict__ hs, const float* __restrict__ gs)
{
    int r    = blockIdx.x;
    int mat  = threadIdx.x >> 5;
    int lane = threadIdx.x & 31;

    if (mat < 2) {
        const float4* W = (const float4*)((mat == 0) ? Wh : Wg);
        float4 v = W[r * 32 + lane];
        float ss = v.x * v.x + v.y * v.y + v.z * v.z + v.w * v.w;
        #pragma unroll
        for (int o = 16; o; o >>= 1) ss += __shfl_xor_sync(0xffffffffu, ss, o);
        float sc = rsqrtf(ss) * ((mat == 0) ? hs[r] : gs[r] * 11.3137084989847604f);
        g_Whg[r * 64 + lane * 2 + mat] =
            make_float4(v.x * sc, v.y * sc, v.z * sc, v.w * sc);
    } else {
        float v[4]; float ss = 0.f;
        #pragma unroll
        for (int k = 0; k < 4; k++) {
            int d = lane + 32 * k;
            v[k] = Wff[d * DI_ + r];
            ss += v[k] * v[k];
        }
        #pragma unroll
        for (int o = 16; o; o >>= 1) ss += __shfl_xor_sync(0xffffffffu, ss, o);
        float inv = rsqrtf(ss);
        #pragma unroll
        for (int k = 0; k < 4; k++) g_WffT[r * D_ + lane + 32 * k] = v[k] * inv;
    }
}

// ------------------------------------------------------------------
// Main: 128 blocks x 1024 threads (32 warps), 32 batch rows per block.
// smem layout (bytes):
//   whg_s : float4[170*65]   0      .. 176800  (65 f4/row: 64 data + 1 pad)
//   emb_i : float4[1024]     176800 .. 193184  (idx = d4*32 + k*8 + bg)
//                            (aliased as x_s[32][128] after phase 2)
//   a_t   : float [170*32]   193184 .. 214944
//   wacc  : float [32]       214944 .. 215072
//   flag  : int              215072 .. 215076
// ------------------------------------------------------------------
#define SMEM_BYTES 215104

__global__ __launch_bounds__(THREADS) void main_kernel(
    const int*   __restrict__ input_ids,
    const int*   __restrict__ target_ids,
    const int*   __restrict__ neg_ids,
    const float* __restrict__ W_in,
    const float* __restrict__ W_out,
    const float* __restrict__ logit_scale,
    float*       __restrict__ out)
{
    extern __shared__ __align__(16) char smem[];
    float4* whg_s = (float4*)smem;
    float4* emb_i = (float4*)(smem + 176800);
    float*  x_s   = (float*)(smem + 176800);   // alias (emb dead after ph.2)
    float*  a_t   = (float*)(smem + 193184);
    float*  wacc  = (float*)(smem + 214944);
    int*    sflag = (int*)(smem + 215072);

    const int tid  = threadIdx.x;
    const int lane = tid & 31;
    const int warp = tid >> 5;
    const int b0   = blockIdx.x * BT_;

    // ---- stage all whg rows (coalesced; 65-f4 row stride) ----
    {
        const float4* src = g_Whg;
        for (int f = tid; f < DI_ * 64; f += THREADS)
            whg_s[(f >> 6) * 65 + (f & 63)] = src[f];
    }

    // ---- Phase 1: gather + l2-normalize 32 input embeddings (1 per warp) ----
    {
        int b   = warp;
        int row = input_ids[b0 + b];
        float4 v = ((const float4*)(W_in + (size_t)row * D_))[lane];
        float ss = v.x * v.x + v.y * v.y + v.z * v.z + v.w * v.w;
        #pragma unroll
        for (int o = 16; o; o >>= 1) ss += __shfl_xor_sync(0xffffffffu, ss, o);
        float inv = rsqrtf(ss);
        emb_i[lane * 32 + (b & 3) * 8 + (b >> 2)] =
            make_float4(v.x * inv, v.y * inv, v.z * inv, v.w * inv);
    }
    __syncthreads();

    // ---- Phase 2: a[b][i] = silu(g)*h; task = (i, 4-b group) ----
    #pragma unroll 1
    for (int idx = tid; idx < DI_ * 8; idx += THREADS) {
        int bg = idx & 7;
        int i  = idx >> 3;
        const ulonglong2* wrow = (const ulonglong2*)&whg_s[i * 65];
        const ulonglong2* eb   = (const ulonglong2*)emb_i;
        u64 hacc[4] = {0, 0, 0, 0};
        u64 gacc[4] = {0, 0, 0, 0};
        #pragma unroll 4
        for (int d4 = 0; d4 < 32; d4++) {
            ulonglong2 wh = wrow[d4 * 2];
            ulonglong2 wg = wrow[d4 * 2 + 1];
            #pragma unroll
            for (int k = 0; k < 4; k++) {
                ulonglong2 ev = eb[d4 * 32 + k * 8 + bg];
                hacc[k] = fma2(ev.x, wh.x, hacc[k]);
                hacc[k] = fma2(ev.y, wh.y, hacc[k]);
                gacc[k] = fma2(ev.x, wg.x, gacc[k]);
                gacc[k] = fma2(ev.y, wg.y, gacc[k]);
            }
        }
        #pragma unroll
        for (int k = 0; k < 4; k++) {
            float2 hp = unpk(hacc[k]);
            float2 gp = unpk(gacc[k]);
            float h = hp.x + hp.y;
            float g = gp.x + gp.y;
            float sg = g / (1.f + __expf(-g));
            a_t[i * 32 + 4 * bg + k] = sg * h;
        }
    }
    __syncthreads();

    // ---- Phase 3: x[b][d] = sum_i a[b][i]*WffT[i][d]; 128 d x 8 bq (4 b each) ----
    {
        int d  = tid & 127;
        int bq = tid >> 7;             // 0..7, owns b in [bq*4, bq*4+4)
        u64 acc[2] = {0, 0};
        const float* wcol = g_WffT + d;
        #pragma unroll 2
        for (int i = 0; i < DI_; i++) {
            float w = __ldg(wcol + i * D_);                 // coalesced, L1-hot
            u64 ww = pk2(w, w);
            ulonglong2 aa = *(const ulonglong2*)&a_t[i * 32 + bq * 4];  // bcast
            acc[0] = fma2(aa.x, ww, acc[0]);
            acc[1] = fma2(aa.y, ww, acc[1]);
        }
        __syncthreads();               // all a_t reads done before x overwrite? (x aliases emb, not a_t)
        #pragma unroll
        for (int p = 0; p < 2; p++) {
            float2 xp = unpk(acc[p]);
            int b = bq * 4 + 2 * p;
            x_s[b * 128 + d]       = xp.x;
            x_s[(b + 1) * 128 + d] = xp.y;
        }
    }
    __syncthreads();

    // ---- Phase 4: 6 gathered logits per row; warp = 1 batch row ----
    float local = 0.f;
    {
        int b  = warp;
        int gb = b0 + b;
        int rows[6]; float4 wv[6]; float lsc[6];
        #pragma unroll
        for (int j = 0; j < 6; j++)
            rows[j] = (j == 0) ? target_ids[gb] : neg_ids[gb * NEG_ + (j - 1)];
        #pragma unroll
        for (int j = 0; j < 6; j++)
            wv[j] = ((const float4*)(W_out + (size_t)rows[j] * D_))[lane];
        #pragma unroll
        for (int j = 0; j < 6; j++) lsc[j] = logit_scale[rows[j]];

        float4 x4 = ((const float4*)(x_s + b * 128))[lane];
        #pragma unroll
        for (int j = 0; j < 6; j++) {
            float dot = wv[j].x * x4.x + wv[j].y * x4.y + wv[j].z * x4.z + wv[j].w * x4.w;
            float ss  = wv[j].x * wv[j].x + wv[j].y * wv[j].y + wv[j].z * wv[j].z + wv[j].w * wv[j].w;
            #pragma unroll
            for (int o = 16; o; o >>= 1) {
                dot += __shfl_xor_sync(0xffffffffu, dot, o);
                ss  += __shfl_xor_sync(0xffffffffu, ss, o);
            }
            if (lane == 0) {
                float logit = dot * rsqrtf(ss) * lsc[j] * 11.3137084989847604f;
                float z = (j == 0) ? logit : -logit;
                float ls = fminf(z, 0.f) - log1pf(__expf(-fabsf(z)));
                local += ls * ((j == 0) ? (1.f / B_) : (1.f / (B_ * NEG_)));
            }
        }
    }
    if (lane == 0) wacc[warp] = local;
    __syncthreads();

    // ---- block partial + fused deterministic final reduction ----
    if (tid == 0) {
        float s = 0.f;
        #pragma unroll
        for (int w = 0; w < 32; w++) s += wacc[w];
        g_partial[blockIdx.x] = s;
        __threadfence();
        unsigned int t = atomicAdd(&g_ticket, 1u);
        sflag[0] = (t == NBLK - 1) ? 1 : 0;
    }
    __syncthreads();
    if (sflag[0]) {
        __threadfence();
        float* red = a_t;  // reuse smem
        if (tid < NBLK) red[tid] = g_partial[tid];
        __syncthreads();
        #pragma unroll
        for (int o = NBLK / 2; o; o >>= 1) {
            if (tid < o) red[tid] += red[tid + o];
            __syncthreads();
        }
        if (tid == 0) {
            out[0] = -red[0];
            g_ticket = 0;   // reset for next graph replay
        }
    }
}

extern "C" void kernel_launch(void* const* d_in, const int* in_sizes, int n_in,
                              void* d_out, int out_size)
{
    const int*   input_ids   = (const int*)  d_in[0];
    const int*   target_ids  = (const int*)  d_in[1];
    const int*   neg_ids     = (const int*)  d_in[2];
    const float* W_in        = (const float*)d_in[3];
    const float* W_out       = (const float*)d_in[4];
    const float* W_hidden    = (const float*)d_in[5];
    const float* W_gate      = (const float*)d_in[6];
    const float* W_ff_out    = (const float*)d_in[7];
    const float* hidden_sc   = (const float*)d_in[8];
    const float* gate_sc     = (const float*)d_in[9];
    const float* logit_scale = (const float*)d_in[10];
    float* out = (float*)d_out;

    cudaFuncSetAttribute(main_kernel, cudaFuncAttributeMaxDynamicSharedMemorySize, SMEM_BYTES);

    prep_kernel<<<DI_, 96>>>(W_hidden, W_gate, W_ff_out, hidden_sc, gate_sc);
    main_kernel<<<NBLK, THREADS, SMEM_BYTES>>>(input_ids, target_ids, neg_ids,
                                               W_in, W_out, logit_scale, out);
}

// round 5
// speedup vs baseline: 1.7948x; 1.1944x over previous
#include <cuda_runtime.h>
#include <math.h>

#define V_   100000
#define D_   128
#define B_   4096
#define NEG_ 5
#define DI_  170
#define BT_  32
#define NBLK (B_ / BT_)      // 128
#define THREADS 1024

typedef unsigned long long u64;

__device__ __forceinline__ u64 fma2(u64 a, u64 b, u64 c) {
    u64 d;
    asm("fma.rn.f32x2 %0, %1, %2, %3;" : "=l"(d) : "l"(a), "l"(b), "l"(c));
    return d;
}
__device__ __forceinline__ u64 pk2(float lo, float hi) {
    u64 r;
    asm("mov.b64 %0, {%1, %2};" : "=l"(r) : "f"(lo), "f"(hi));
    return r;
}
__device__ __forceinline__ float2 unpk(u64 v) {
    float2 r;
    asm("mov.b64 {%0, %1}, %2;" : "=f"(r.x), "=f"(r.y) : "l"(v));
    return r;
}

// ---- device scratch ----
__device__ float g_partial[NBLK];
__device__ unsigned int g_ticket;

// ------------------------------------------------------------------
// Single fused kernel: 128 blocks x 1024 threads, 32 batch rows/block.
// Each block recomputes the (tiny) weight normalizations into its own
// smem — removes the prep kernel and its launch serialization.
//
// smem layout (bytes):
//   whg_s : float4[170*65]   0      .. 176800   (phase-2 weights)
//     after phase 2, region aliased as:
//       wffs : float[128*173] 0      .. 88576   (raw Wff rows, pad 173)
//       inv_s: float[176]     100000 .. 100704  (column rsqrt norms)
//   emb_i : float4[1024]     176800 .. 193184   (idx = d4*32 + k*8 + bg)
//     after phase 2, aliased as x_s[32][128]
//   a_t   : float [170*32]   193184 .. 214944
//   wacc  : float [32]       214944 .. 215072
//   flag  : int              215072 .. 215076
// ------------------------------------------------------------------
#define SMEM_BYTES 215104

__global__ __launch_bounds__(THREADS) void main_kernel(
    const int*   __restrict__ input_ids,
    const int*   __restrict__ target_ids,
    const int*   __restrict__ neg_ids,
    const float* __restrict__ W_in,
    const float* __restrict__ W_out,
    const float* __restrict__ Wh,
    const float* __restrict__ Wg,
    const float* __restrict__ Wff,
    const float* __restrict__ hs,
    const float* __restrict__ gs,
    const float* __restrict__ logit_scale,
    float*       __restrict__ out)
{
    extern __shared__ __align__(16) char smem[];
    float4* whg_s = (float4*)smem;
    float*  wffs  = (float*)smem;                // alias after phase 2
    float*  inv_s = (float*)(smem + 100000);     // alias after phase 2
    float4* emb_i = (float4*)(smem + 176800);
    float*  x_s   = (float*)(smem + 176800);     // alias after phase 2
    float*  a_t   = (float*)(smem + 193184);
    float*  wacc  = (float*)(smem + 214944);
    int*    sflag = (int*)(smem + 215072);

    const int tid  = threadIdx.x;
    const int lane = tid & 31;
    const int warp = tid >> 5;
    const int b0   = blockIdx.x * BT_;

    // ---- Phase 1: gather + l2-normalize 32 input embeddings (1 per warp) ----
    {
        int b   = warp;
        int row = input_ids[b0 + b];
        float4 v = ((const float4*)(W_in + (size_t)row * D_))[lane];
        float ss = v.x * v.x + v.y * v.y + v.z * v.z + v.w * v.w;
        #pragma unroll
        for (int o = 16; o; o >>= 1) ss += __shfl_xor_sync(0xffffffffu, ss, o);
        float inv = rsqrtf(ss);
        emb_i[lane * 32 + (b & 3) * 8 + (b >> 2)] =
            make_float4(v.x * inv, v.y * inv, v.z * inv, v.w * inv);
    }

    // ---- Stage whg: normalize Wh/Wg rows in-block (340 warp-tasks) ----
    #pragma unroll 1
    for (int t = warp; t < 2 * DI_; t += 32) {
        int mat = (t >= DI_);
        int r   = mat ? (t - DI_) : t;
        const float4* W = (const float4*)(mat ? Wg : Wh);
        float4 v = W[r * 32 + lane];
        float ss = v.x * v.x + v.y * v.y + v.z * v.z + v.w * v.w;
        #pragma unroll
        for (int o = 16; o; o >>= 1) ss += __shfl_xor_sync(0xffffffffu, ss, o);
        float sc = rsqrtf(ss) * (mat ? gs[r] * 11.3137084989847604f : hs[r]);
        whg_s[r * 65 + lane * 2 + mat] =
            make_float4(v.x * sc, v.y * sc, v.z * sc, v.w * sc);
    }
    __syncthreads();

    // ---- Phase 2: a[b][i] = silu(g)*h; task = (i, 4-b group) ----
    #pragma unroll 1
    for (int idx = tid; idx < DI_ * 8; idx += THREADS) {
        int bg = idx & 7;
        int i  = idx >> 3;
        const ulonglong2* wrow = (const ulonglong2*)&whg_s[i * 65];
        const ulonglong2* eb   = (const ulonglong2*)emb_i;
        u64 hacc[4] = {0, 0, 0, 0};
        u64 gacc[4] = {0, 0, 0, 0};
        #pragma unroll 4
        for (int d4 = 0; d4 < 32; d4++) {
            ulonglong2 wh = wrow[d4 * 2];
            ulonglong2 wg = wrow[d4 * 2 + 1];
            #pragma unroll
            for (int k = 0; k < 4; k++) {
                ulonglong2 ev = eb[d4 * 32 + k * 8 + bg];
                hacc[k] = fma2(ev.x, wh.x, hacc[k]);
                hacc[k] = fma2(ev.y, wh.y, hacc[k]);
                gacc[k] = fma2(ev.x, wg.x, gacc[k]);
                gacc[k] = fma2(ev.y, wg.y, gacc[k]);
            }
        }
        #pragma unroll
        for (int k = 0; k < 4; k++) {
            float2 hp = unpk(hacc[k]);
            float2 gp = unpk(gacc[k]);
            float h = hp.x + hp.y;
            float g = gp.x + gp.y;
            float sg = g / (1.f + __expf(-g));
            a_t[i * 32 + 4 * bg + k] = sg * h;
        }
    }
    __syncthreads();

    // ---- Stage raw Wff rows [d][i] (pad 173) into whg alias (coalesced) ----
    {
        #pragma unroll
        for (int rr = 0; rr < 4; rr++) {
            int d = warp * 4 + rr;
            #pragma unroll
            for (int k = 0; k < 6; k++) {
                int c = lane + 32 * k;
                if (c < DI_) wffs[d * 173 + c] = Wff[d * DI_ + c];
            }
        }
    }
    __syncthreads();

    // ---- Column norms inv[i] = rsqrt(sum_d Wff[d][i]^2) (warps 0-5) ----
    if (warp < 6) {
        int c = warp * 32 + lane;
        float ss = 0.f;
        #pragma unroll 4
        for (int d = 0; d < D_; d++) {
            float w = wffs[d * 173 + ((c < DI_) ? c : 0)];
            ss += w * w;
        }
        if (c < DI_) inv_s[c] = rsqrtf(ss);
    }
    __syncthreads();

    // ---- Fold inv into a_t (5440 elems) ----
    #pragma unroll 1
    for (int idx = tid; idx < DI_ * 32; idx += THREADS)
        a_t[idx] *= inv_s[idx >> 5];
    __syncthreads();

    // ---- Phase 3: x[b][d] = sum_i a'[b][i]*Wff[d][i]; all from smem ----
    {
        int d  = tid & 127;
        int bq = tid >> 7;             // 0..7, owns b in [bq*4, bq*4+4)
        u64 acc[2] = {0, 0};
        const float* wrow = wffs + d * 173;
        #pragma unroll 5
        for (int i = 0; i < DI_; i++) {
            float w = wrow[i];                                  // conflict-free LDS
            u64 ww = pk2(w, w);
            ulonglong2 aa = *(const ulonglong2*)&a_t[i * 32 + bq * 4];  // bcast
            acc[0] = fma2(aa.x, ww, acc[0]);
            acc[1] = fma2(aa.y, ww, acc[1]);
        }
        __syncthreads();               // emb reads done (ph.2) before x_s write
        #pragma unroll
        for (int p = 0; p < 2; p++) {
            float2 xp = unpk(acc[p]);
            int b = bq * 4 + 2 * p;
            x_s[b * 128 + d]       = xp.x;
            x_s[(b + 1) * 128 + d] = xp.y;
        }
    }
    __syncthreads();

    // ---- Phase 4: 6 gathered logits per row; warp = 1 batch row ----
    float local = 0.f;
    {
        int b  = warp;
        int gb = b0 + b;
        int rows[6]; float4 wv[6]; float lsc[6];
        #pragma unroll
        for (int j = 0; j < 6; j++)
            rows[j] = (j == 0) ? target_ids[gb] : neg_ids[gb * NEG_ + (j - 1)];
        #pragma unroll
        for (int j = 0; j < 6; j++)
            wv[j] = ((const float4*)(W_out + (size_t)rows[j] * D_))[lane];
        #pragma unroll
        for (int j = 0; j < 6; j++) lsc[j] = logit_scale[rows[j]];

        float4 x4 = ((const float4*)(x_s + b * 128))[lane];
        #pragma unroll
        for (int j = 0; j < 6; j++) {
            float dot = wv[j].x * x4.x + wv[j].y * x4.y + wv[j].z * x4.z + wv[j].w * x4.w;
            float ss  = wv[j].x * wv[j].x + wv[j].y * wv[j].y + wv[j].z * wv[j].z + wv[j].w * wv[j].w;
            #pragma unroll
            for (int o = 16; o; o >>= 1) {
                dot += __shfl_xor_sync(0xffffffffu, dot, o);
                ss  += __shfl_xor_sync(0xffffffffu, ss, o);
            }
            if (lane == 0) {
                float logit = dot * rsqrtf(ss) * lsc[j] * 11.3137084989847604f;
                float z = (j == 0) ? logit : -logit;
                float ls = fminf(z, 0.f) - log1pf(__expf(-fabsf(z)));
                local += ls * ((j == 0) ? (1.f / B_) : (1.f / (B_ * NEG_)));
            }
        }
    }
    if (lane == 0) wacc[warp] = local;
    __syncthreads();

    // ---- block partial + fused deterministic final reduction ----
    if (tid == 0) {
        float s = 0.f;
        #pragma unroll
        for (int w = 0; w < 32; w++) s += wacc[w];
        g_partial[blockIdx.x] = s;
        __threadfence();
        unsigned int t = atomicAdd(&g_ticket, 1u);
        sflag[0] = (t == NBLK - 1) ? 1 : 0;
    }
    __syncthreads();
    if (sflag[0]) {
        __threadfence();
        float* red = a_t;  // reuse smem
        if (tid < NBLK) red[tid] = g_partial[tid];
        __syncthreads();
        #pragma unroll
        for (int o = NBLK / 2; o; o >>= 1) {
            if (tid < o) red[tid] += red[tid + o];
            __syncthreads();
        }
        if (tid == 0) {
            out[0] = -red[0];
            g_ticket = 0;   // reset for next graph replay
        }
    }
}

extern "C" void kernel_launch(void* const* d_in, const int* in_sizes, int n_in,
                              void* d_out, int out_size)
{
    const int*   input_ids   = (const int*)  d_in[0];
    const int*   target_ids  = (const int*)  d_in[1];
    const int*   neg_ids     = (const int*)  d_in[2];
    const float* W_in        = (const float*)d_in[3];
    const float* W_out       = (const float*)d_in[4];
    const float* W_hidden    = (const float*)d_in[5];
    const float* W_gate      = (const float*)d_in[6];
    const float* W_ff_out    = (const float*)d_in[7];
    const float* hidden_sc   = (const float*)d_in[8];
    const float* gate_sc     = (const float*)d_in[9];
    const float* logit_scale = (const float*)d_in[10];
    float* out = (float*)d_out;

    cudaFuncSetAttribute(main_kernel, cudaFuncAttributeMaxDynamicSharedMemorySize, SMEM_BYTES);

    main_kernel<<<NBLK, THREADS, SMEM_BYTES>>>(input_ids, target_ids, neg_ids,
                                               W_in, W_out, W_hidden, W_gate,
                                               W_ff_out, hidden_sc, gate_sc,
                                               logit_scale, out);
}

// round 6
// speedup vs baseline: 1.9914x; 1.1096x over previous
#include <cuda_runtime.h>
#include <math.h>

#define V_   100000
#define D_   128
#define B_   4096
#define NEG_ 5
#define DI_  170
#define BT_  32
#define NBLK (B_ / BT_)      // 128
#define THREADS 1024

typedef unsigned long long u64;

__device__ __forceinline__ u64 fma2(u64 a, u64 b, u64 c) {
    u64 d;
    asm("fma.rn.f32x2 %0, %1, %2, %3;" : "=l"(d) : "l"(a), "l"(b), "l"(c));
    return d;
}
__device__ __forceinline__ u64 pk2(float lo, float hi) {
    u64 r;
    asm("mov.b64 %0, {%1, %2};" : "=l"(r) : "f"(lo), "f"(hi));
    return r;
}
__device__ __forceinline__ float2 unpk(u64 v) {
    float2 r;
    asm("mov.b64 {%0, %1}, %2;" : "=f"(r.x), "=f"(r.y) : "l"(v));
    return r;
}

// ---- device scratch ----
__device__ float g_partial[NBLK];
__device__ unsigned int g_ticket;

// ------------------------------------------------------------------
// Single fused kernel: 128 blocks x 1024 threads, 32 batch rows/block.
//
// smem layout (bytes):
//   whg_s : float4[170*65]   0      .. 176800   (phase-2 weights)
//     after phase 2, region aliased as:
//       wffs : float[128*173] 0      .. 88576   (raw Wff rows, pad 173)
//       inv_s: float[176]     100000 .. 100704  (column rsqrt norms)
//   emb_i : float4[1024]     176800 .. 193184   (idx = d4*32 + k*8 + bg)
//     after phase 2, aliased as x_s[32][128]
//   a_t   : float [170*32]   193184 .. 214944
//   wacc  : float [32]       214944 .. 215072
//   flag  : int              215072 .. 215076
// ------------------------------------------------------------------
#define SMEM_BYTES 215104

__global__ __launch_bounds__(THREADS) void main_kernel(
    const int*   __restrict__ input_ids,
    const int*   __restrict__ target_ids,
    const int*   __restrict__ neg_ids,
    const float* __restrict__ W_in,
    const float* __restrict__ W_out,
    const float* __restrict__ Wh,
    const float* __restrict__ Wg,
    const float* __restrict__ Wff,
    const float* __restrict__ hs,
    const float* __restrict__ gs,
    const float* __restrict__ logit_scale,
    float*       __restrict__ out)
{
    extern __shared__ __align__(16) char smem[];
    float4* whg_s = (float4*)smem;
    float*  wffs  = (float*)smem;                // alias after phase 2
    float*  inv_s = (float*)(smem + 100000);     // alias after phase 2
    float4* emb_i = (float4*)(smem + 176800);
    float*  x_s   = (float*)(smem + 176800);     // alias after phase 2
    float*  a_t   = (float*)(smem + 193184);
    float*  wacc  = (float*)(smem + 214944);
    int*    sflag = (int*)(smem + 215072);

    const int tid  = threadIdx.x;
    const int lane = tid & 31;
    const int warp = tid >> 5;
    const int b0   = blockIdx.x * BT_;

    // ---- Phase 1: gather + l2-normalize 32 input embeddings (1 per warp) ----
    {
        int b   = warp;
        int row = input_ids[b0 + b];
        float4 v = ((const float4*)(W_in + (size_t)row * D_))[lane];
        float ss = v.x * v.x + v.y * v.y + v.z * v.z + v.w * v.w;
        #pragma unroll
        for (int o = 16; o; o >>= 1) ss += __shfl_xor_sync(0xffffffffu, ss, o);
        float inv = rsqrtf(ss);
        emb_i[lane * 32 + (b & 3) * 8 + (b >> 2)] =
            make_float4(v.x * inv, v.y * inv, v.z * inv, v.w * inv);
    }

    // ---- Stage whg: normalize Wh/Wg rows in-block (340 warp-tasks) ----
    #pragma unroll 1
    for (int t = warp; t < 2 * DI_; t += 32) {
        int mat = (t >= DI_);
        int r   = mat ? (t - DI_) : t;
        const float4* W = (const float4*)(mat ? Wg : Wh);
        float4 v = W[r * 32 + lane];
        float ss = v.x * v.x + v.y * v.y + v.z * v.z + v.w * v.w;
        #pragma unroll
        for (int o = 16; o; o >>= 1) ss += __shfl_xor_sync(0xffffffffu, ss, o);
        float sc = rsqrtf(ss) * (mat ? gs[r] * 11.3137084989847604f : hs[r]);
        whg_s[r * 65 + lane * 2 + mat] =
            make_float4(v.x * sc, v.y * sc, v.z * sc, v.w * sc);
    }
    __syncthreads();

    // ---- Phase 2: a[b][i]=silu(g)*h; thread = (i-pair, 4-b group), 680 tasks ----
    if (tid < 85 * 8) {
        int bg = tid & 7;
        int pp = tid >> 3;              // 0..84 -> rows i0 = 2pp, 2pp+1
        const ulonglong2* w0 = (const ulonglong2*)&whg_s[(2 * pp) * 65];
        const ulonglong2* w1 = (const ulonglong2*)&whg_s[(2 * pp + 1) * 65];
        const ulonglong2* eb = (const ulonglong2*)emb_i;
        u64 h0[4] = {0,0,0,0}, g0[4] = {0,0,0,0};
        u64 h1[4] = {0,0,0,0}, g1[4] = {0,0,0,0};
        #pragma unroll 2
        for (int d4 = 0; d4 < 32; d4++) {
            ulonglong2 wh0 = w0[d4 * 2];
            ulonglong2 wg0 = w0[d4 * 2 + 1];
            ulonglong2 wh1 = w1[d4 * 2];
            ulonglong2 wg1 = w1[d4 * 2 + 1];
            #pragma unroll
            for (int k = 0; k < 4; k++) {
                ulonglong2 ev = eb[d4 * 32 + k * 8 + bg];
                h0[k] = fma2(ev.x, wh0.x, h0[k]);
                h0[k] = fma2(ev.y, wh0.y, h0[k]);
                g0[k] = fma2(ev.x, wg0.x, g0[k]);
                g0[k] = fma2(ev.y, wg0.y, g0[k]);
                h1[k] = fma2(ev.x, wh1.x, h1[k]);
                h1[k] = fma2(ev.y, wh1.y, h1[k]);
                g1[k] = fma2(ev.x, wg1.x, g1[k]);
                g1[k] = fma2(ev.y, wg1.y, g1[k]);
            }
        }
        #pragma unroll
        for (int k = 0; k < 4; k++) {
            float2 hp = unpk(h0[k]); float2 gp = unpk(g0[k]);
            float h = hp.x + hp.y, g = gp.x + gp.y;
            a_t[(2 * pp) * 32 + 4 * bg + k] = h * (g / (1.f + __expf(-g)));
            hp = unpk(h1[k]); gp = unpk(g1[k]);
            h = hp.x + hp.y; g = gp.x + gp.y;
            a_t[(2 * pp + 1) * 32 + 4 * bg + k] = h * (g / (1.f + __expf(-g)));
        }
    }
    __syncthreads();

    // ---- Stage raw Wff rows [d][i] (pad 173) into whg alias (coalesced) ----
    {
        #pragma unroll
        for (int rr = 0; rr < 4; rr++) {
            int d = warp * 4 + rr;
            #pragma unroll
            for (int k = 0; k < 6; k++) {
                int c = lane + 32 * k;
                if (c < DI_) wffs[d * 173 + c] = Wff[d * DI_ + c];
            }
        }
    }
    __syncthreads();

    // ---- Column norms: all 32 warps, warp handles cols warp+32k ----
    #pragma unroll 1
    for (int c = warp; c < DI_; c += 32) {
        float ss = 0.f;
        #pragma unroll
        for (int m = 0; m < 4; m++) {
            float w = wffs[(lane + 32 * m) * 173 + c];
            ss += w * w;
        }
        #pragma unroll
        for (int o = 16; o; o >>= 1) ss += __shfl_xor_sync(0xffffffffu, ss, o);
        if (lane == 0) inv_s[c] = rsqrtf(ss);
    }
    __syncthreads();

    // ---- Fold inv into a_t (5440 elems) ----
    #pragma unroll 1
    for (int idx = tid; idx < DI_ * 32; idx += THREADS)
        a_t[idx] *= inv_s[idx >> 5];
    __syncthreads();

    // ---- Phase 3: x[b][d] = sum_i a'[b][i]*Wff[d][i]; all from smem ----
    {
        int d  = tid & 127;
        int bq = tid >> 7;             // 0..7, owns b in [bq*4, bq*4+4)
        u64 acc[2] = {0, 0};
        const float* wrow = wffs + d * 173;
        #pragma unroll 5
        for (int i = 0; i < DI_; i++) {
            float w = wrow[i];                                  // conflict-free LDS
            u64 ww = pk2(w, w);
            ulonglong2 aa = *(const ulonglong2*)&a_t[i * 32 + bq * 4];  // bcast
            acc[0] = fma2(aa.x, ww, acc[0]);
            acc[1] = fma2(aa.y, ww, acc[1]);
        }
        #pragma unroll
        for (int p = 0; p < 2; p++) {
            float2 xp = unpk(acc[p]);
            int b = bq * 4 + 2 * p;
            x_s[b * 128 + d]       = xp.x;
            x_s[(b + 1) * 128 + d] = xp.y;
        }
    }
    __syncthreads();

    // ---- Phase 4: 6 gathered logits per row; warp = 1 batch row ----
    float local = 0.f;
    {
        int b  = warp;
        int gb = b0 + b;
        int rows[6]; float4 wv[6]; float lsc[6];
        #pragma unroll
        for (int j = 0; j < 6; j++)
            rows[j] = (j == 0) ? target_ids[gb] : neg_ids[gb * NEG_ + (j - 1)];
        #pragma unroll
        for (int j = 0; j < 6; j++)
            wv[j] = ((const float4*)(W_out + (size_t)rows[j] * D_))[lane];
        #pragma unroll
        for (int j = 0; j < 6; j++) lsc[j] = logit_scale[rows[j]];

        float4 x4 = ((const float4*)(x_s + b * 128))[lane];
        #pragma unroll
        for (int j = 0; j < 6; j++) {
            float dot = wv[j].x * x4.x + wv[j].y * x4.y + wv[j].z * x4.z + wv[j].w * x4.w;
            float ss  = wv[j].x * wv[j].x + wv[j].y * wv[j].y + wv[j].z * wv[j].z + wv[j].w * wv[j].w;
            #pragma unroll
            for (int o = 16; o; o >>= 1) {
                dot += __shfl_xor_sync(0xffffffffu, dot, o);
                ss  += __shfl_xor_sync(0xffffffffu, ss, o);
            }
            if (lane == 0) {
                float logit = dot * rsqrtf(ss) * lsc[j] * 11.3137084989847604f;
                float z = (j == 0) ? logit : -logit;
                float ls = fminf(z, 0.f) - log1pf(__expf(-fabsf(z)));
                local += ls * ((j == 0) ? (1.f / B_) : (1.f / (B_ * NEG_)));
            }
        }
    }
    if (lane == 0) wacc[warp] = local;
    __syncthreads();

    // ---- block partial + fused deterministic final reduction ----
    if (tid == 0) {
        float s = 0.f;
        #pragma unroll
        for (int w = 0; w < 32; w++) s += wacc[w];
        g_partial[blockIdx.x] = s;
        __threadfence();
        unsigned int t = atomicAdd(&g_ticket, 1u);
        sflag[0] = (t == NBLK - 1) ? 1 : 0;
    }
    __syncthreads();
    if (sflag[0]) {
        __threadfence();
        float* red = a_t;  // reuse smem
        if (tid < NBLK) red[tid] = g_partial[tid];
        __syncthreads();
        #pragma unroll
        for (int o = NBLK / 2; o; o >>= 1) {
            if (tid < o) red[tid] += red[tid + o];
            __syncthreads();
        }
        if (tid == 0) {
            out[0] = -red[0];
            g_ticket = 0;   // reset for next graph replay
        }
    }
}

extern "C" void kernel_launch(void* const* d_in, const int* in_sizes, int n_in,
                              void* d_out, int out_size)
{
    const int*   input_ids   = (const int*)  d_in[0];
    const int*   target_ids  = (const int*)  d_in[1];
    const int*   neg_ids     = (const int*)  d_in[2];
    const float* W_in        = (const float*)d_in[3];
    const float* W_out       = (const float*)d_in[4];
    const float* W_hidden    = (const float*)d_in[5];
    const float* W_gate      = (const float*)d_in[6];
    const float* W_ff_out    = (const float*)d_in[7];
    const float* hidden_sc   = (const float*)d_in[8];
    const float* gate_sc     = (const float*)d_in[9];
    const float* logit_scale = (const float*)d_in[10];
    float* out = (float*)d_out;

    cudaFuncSetAttribute(main_kernel, cudaFuncAttributeMaxDynamicSharedMemorySize, SMEM_BYTES);

    main_kernel<<<NBLK, THREADS, SMEM_BYTES>>>(input_ids, target_ids, neg_ids,
                                               W_in, W_out, W_hidden, W_gate,
                                               W_ff_out, hidden_sc, gate_sc,
                                               logit_scale, out);
}